// round 7
// baseline (speedup 1.0000x reference)
#include <cuda_runtime.h>
#include <math.h>

// SofaNetEllipse: fused MLP(1->128->128->128->1) forward + JVP + ellipse epilogue.
// R6: 512 threads/block (16 warps -> 4 warps/SMSP) with 4x8 packed register tile
// to hide LDS latency and saturate the FMA pipe (was 58.7% at 256 threads).

typedef unsigned long long ull;

namespace {
constexpr int HD      = 128;    // hidden dim
constexpr int NCUR    = 128;    // number of curves
constexpr int LFULL   = 4097;
constexpr int BHALF   = 2049;   // L//2 + 1
constexpr int BT      = 128;    // samples per block tile
constexpr int NTILES  = (BHALF + BT - 1) / BT;  // 17
constexpr int WSTRIDE = 129;    // padded transposed-weight row stride (floats)
constexpr int NTHREADS = 512;
constexpr size_t SMEM_HD    = (size_t)HD * BT * 8;        // 131072 B: {h,dh} f32x2
constexpr size_t SMEM_W     = (size_t)HD * WSTRIDE * 4;   // 66048 B
constexpr size_t SMEM_BYTES = SMEM_HD + SMEM_W;           // 197120 B
}

// packed f32x2 fma (Blackwell sm_100+): d.lo = a.lo*b.lo+c.lo ; d.hi likewise
__device__ __forceinline__ ull ffma2(ull a, ull b, ull c) {
    ull d;
    asm("fma.rn.f32x2 %0, %1, %2, %3;" : "=l"(d) : "l"(a), "l"(b), "l"(c));
    return d;
}
__device__ __forceinline__ ull dup2(float x) {            // {x, x}
    ull r; asm("mov.b64 %0, {%1, %1};" : "=l"(r) : "f"(x)); return r;
}
__device__ __forceinline__ ull pack2(float x, float y) {  // {x, y}
    ull r; asm("mov.b64 %0, {%1, %2};" : "=l"(r) : "f"(x), "f"(y)); return r;
}
__device__ __forceinline__ float2 unpack2(ull v) {
    float lo, hi;
    asm("mov.b64 {%0, %1}, %2;" : "=f"(lo), "=f"(hi) : "l"(v));
    return make_float2(lo, hi);
}

// Stage one 128x128 weight matrix transposed into SMEM: wsh[j*WSTRIDE + i] = W[i][j].
// Coalesced float4 global reads; stride-129 scatter (one-shot, cheap).
__device__ __forceinline__ void stage_w(float* __restrict__ wsh,
                                        const float* __restrict__ wg, int tid) {
    const float4* g = reinterpret_cast<const float4*>(wg);
    const int j4 = tid & 31;        // which group of 4 columns
    const int i0 = tid >> 5;        // base row (0..15)
#pragma unroll
    for (int k = 0; k < 8; k++) {
        const int i = i0 + k * 16;
        const float4 v = g[i * 32 + j4];
        const int j = j4 * 4;
        wsh[(j + 0) * WSTRIDE + i] = v.x;
        wsh[(j + 1) * WSTRIDE + i] = v.y;
        wsh[(j + 2) * WSTRIDE + i] = v.z;
        wsh[(j + 3) * WSTRIDE + i] = v.w;
    }
}

// One hidden layer (value + tangent fused in f32x2 lanes), relu + relu-mask.
// Tile: 4 output rows x 8 packed samples per thread (512 threads cover 128x128).
// hd: interleaved state {h, dh} as ull, layout [j(128)][b(128)].
// Internal barrier separates GEMM reads from in-place overwrite; caller
// __syncthreads() after (and may stage next W before that barrier).
__device__ __forceinline__ void dense_relu_layer(ull* __restrict__ hd,
                                                 const float* __restrict__ wsh,
                                                 const float* __restrict__ bias_g,
                                                 int ibase, int bg) {
    ull acc[4][8];
#pragma unroll
    for (int r = 0; r < 4; r++)
#pragma unroll
        for (int p = 0; p < 8; p++) acc[r][p] = 0ull;

#pragma unroll 1
    for (int j = 0; j < HD; j++) {
        const float* wr = wsh + j * WSTRIDE + ibase;
        ull wd[4];
#pragma unroll
        for (int r = 0; r < 4; r++) wd[r] = dup2(wr[r]);
        const ull* hrow = hd + j * BT + bg;     // b = bg + 16*p -> conflict-free
        ull hv[8];
#pragma unroll
        for (int p = 0; p < 8; p++) hv[p] = hrow[16 * p];
#pragma unroll
        for (int r = 0; r < 4; r++)
#pragma unroll
            for (int p = 0; p < 8; p++)
                acc[r][p] = ffma2(wd[r], hv[p], acc[r][p]);
    }

    float bb[4];
#pragma unroll
    for (int r = 0; r < 4; r++) bb[r] = bias_g[ibase + r];

    __syncthreads();   // all GEMM reads of hd/wsh complete before overwrite

#pragma unroll
    for (int r = 0; r < 4; r++) {
#pragma unroll
        for (int p = 0; p < 8; p++) {
            const float2 a = unpack2(acc[r][p]);
            const float pre = a.x + bb[r];
            const float h = pre > 0.f ? pre : 0.f;
            const float d = pre > 0.f ? a.y : 0.f;   // relu JVP mask
            hd[(ibase + r) * BT + bg + 16 * p] = pack2(h, d);
        }
    }
}

__global__ void __launch_bounds__(NTHREADS, 1)
sofa_kernel(const float* __restrict__ alpha,
            const float* __restrict__ w0g, const float* __restrict__ w1g,
            const float* __restrict__ w2g, const float* __restrict__ w3g,
            const float* __restrict__ b0g, const float* __restrict__ b1g,
            const float* __restrict__ b2g, const float* __restrict__ b3g,
            const float* __restrict__ sqrtag, float* __restrict__ out) {
    extern __shared__ char smem_raw[];
    ull*   hd  = reinterpret_cast<ull*>(smem_raw);
    float* wsh = reinterpret_cast<float*>(smem_raw + SMEM_HD);

    const int n    = blockIdx.y;
    const int tile = blockIdx.x;
    const int tid  = threadIdx.x;
    const int bg   = tid & 15;       // b-group: samples b = bg + 16*p
    const int ig   = tid >> 4;       // i-group: rows ibase..ibase+3 (0..31)
    const int ibase = ig * 4;
    const int base  = tile * BT;     // first (half-)sample of this tile

    // ---- layer 0: h0 = relu(w0*alpha + b0), dh0 = mask * w0 ; stage W1
    for (int idx = tid; idx < HD * BT; idx += NTHREADS) {
        const int i = idx >> 7;
        const int b = idx & 127;
        const float av  = alpha[base + b];     // base+b <= 2175 < 4097, in-bounds
        const float w   = w0g[n * HD + i];
        const float bb  = b0g[n * HD + i];
        const float pre = fmaf(w, av, bb);
        const float h   = pre > 0.f ? pre : 0.f;
        const float d   = pre > 0.f ? w : 0.f;
        hd[i * BT + b] = pack2(h, d);
    }
    stage_w(wsh, w1g + (size_t)n * HD * HD, tid);
    __syncthreads();

    // ---- layers 1, 2
    dense_relu_layer(hd, wsh, b1g + n * HD, ibase, bg);
    stage_w(wsh, w2g + (size_t)n * HD * HD, tid);   // wsh dead after internal barrier
    __syncthreads();

    dense_relu_layer(hd, wsh, b2g + n * HD, ibase, bg);
    __syncthreads();

    // ---- layer 3: out = w3 . h2 + b3 ; dout = w3 . dh2 ; then ellipse epilogue
    {
        const int bl = tid & 127;
        const int q  = tid >> 7;               // split reduction over i in quarters
        const float* w3n = w3g + n * HD;
        float sv = 0.f, st = 0.f;
#pragma unroll 4
        for (int ii = q * 32; ii < q * 32 + 32; ii++) {
            const float wv = w3n[ii];
            const float2 h = unpack2(hd[ii * BT + bl]);
            sv = fmaf(wv, h.x, sv);
            st = fmaf(wv, h.y, st);
        }
        float* redv = wsh;                      // reuse weight SMEM (dead)
        float* redt = wsh + 4 * BT;
        redv[q * BT + bl] = sv;
        redt[q * BT + bl] = st;
        __syncthreads();

        if (tid < BT) {
            const int jg = base + tid;          // global half-sample index
            if (jg < BHALF) {
                const float v = redv[tid] + redv[BT + tid] + redv[2 * BT + tid]
                              + redv[3 * BT + tid] + b3g[n];
                const float t = redt[tid] + redt[BT + tid] + redt[2 * BT + tid]
                              + redt[3 * BT + tid];
                const float bsq = v * v;                 // b
                const float dbv = 2.f * v * t;           // db (chain rule of square)
                float a = sqrtag[n]; a = a * a;          // a_full
                const size_t NL = (size_t)NCUR * LFULL;

                float s, c;
                sincosf(alpha[jg], &s, &c);
                const size_t o = (size_t)n * LFULL + jg;
                out[o]          = a * (c - 1.f);         // xp
                out[NL + o]     = bsq * s;               // yp
                out[2 * NL + o] = -a * s;                // xp'
                out[3 * NL + o] = fmaf(bsq, c, dbv * s); // yp'

                if (jg < BHALF - 1) {                    // mirror l = 4096 - jg
                    const int l = 2 * (BHALF - 1) - jg;
                    float s2, c2;
                    sincosf(alpha[l], &s2, &c2);
                    const size_t o2 = (size_t)n * LFULL + l;
                    out[o2]          = a * (c2 - 1.f);
                    out[NL + o2]     = bsq * s2;
                    out[2 * NL + o2] = -a * s2;
                    out[3 * NL + o2] = fmaf(bsq, c2, -dbv * s2);  // db mirrored with -
                }
            }
        }
    }
}

extern "C" void kernel_launch(void* const* d_in, const int* in_sizes, int n_in,
                              void* d_out, int out_size) {
    (void)in_sizes; (void)n_in; (void)out_size;
    const float* alpha  = (const float*)d_in[0];
    const float* w0     = (const float*)d_in[1];
    const float* w1     = (const float*)d_in[2];
    const float* w2     = (const float*)d_in[3];
    const float* w3     = (const float*)d_in[4];
    const float* b0     = (const float*)d_in[5];
    const float* b1     = (const float*)d_in[6];
    const float* b2     = (const float*)d_in[7];
    const float* b3     = (const float*)d_in[8];
    const float* sqrt_a = (const float*)d_in[9];
    float* out = (float*)d_out;

    cudaFuncSetAttribute(sofa_kernel, cudaFuncAttributeMaxDynamicSharedMemorySize,
                         (int)SMEM_BYTES);

    dim3 grid(NTILES, NCUR);   // (17, 128)
    sofa_kernel<<<grid, NTHREADS, SMEM_BYTES>>>(alpha, w0, w1, w2, w3,
                                                b0, b1, b2, b3, sqrt_a, out);
}

// round 8
// speedup vs baseline: 1.0262x; 1.0262x over previous
#include <cuda_runtime.h>
#include <math.h>

// SofaNetEllipse: fused MLP(1->128->128->128->1) forward + JVP + ellipse epilogue.
// R7: back to 256 threads / 8x8 packed tile (low smem-crossbar traffic, ~50% L1)
// + software-pipelined j-loop (double-buffered hv/w prefetch) to hide LDS latency
// that capped R5 at fma=58.7%.

typedef unsigned long long ull;

namespace {
constexpr int HD      = 128;    // hidden dim
constexpr int NCUR    = 128;    // number of curves
constexpr int LFULL   = 4097;
constexpr int BHALF   = 2049;   // L//2 + 1
constexpr int BT      = 128;    // samples per block tile
constexpr int NTILES  = (BHALF + BT - 1) / BT;  // 17
constexpr int WSTRIDE = 129;    // padded transposed-weight row stride (floats)
constexpr int NTHREADS = 256;
constexpr size_t SMEM_HD    = (size_t)HD * BT * 8;        // 131072 B: {h,dh} f32x2
constexpr size_t SMEM_W     = (size_t)HD * WSTRIDE * 4;   // 66048 B
constexpr size_t SMEM_BYTES = SMEM_HD + SMEM_W;           // 197120 B
}

// packed f32x2 fma (Blackwell sm_100+): d.lo = a.lo*b.lo+c.lo ; d.hi likewise
__device__ __forceinline__ ull ffma2(ull a, ull b, ull c) {
    ull d;
    asm("fma.rn.f32x2 %0, %1, %2, %3;" : "=l"(d) : "l"(a), "l"(b), "l"(c));
    return d;
}
__device__ __forceinline__ ull dup2(float x) {            // {x, x}
    ull r; asm("mov.b64 %0, {%1, %1};" : "=l"(r) : "f"(x)); return r;
}
__device__ __forceinline__ ull pack2(float x, float y) {  // {x, y}
    ull r; asm("mov.b64 %0, {%1, %2};" : "=l"(r) : "f"(x), "f"(y)); return r;
}
__device__ __forceinline__ float2 unpack2(ull v) {
    float lo, hi;
    asm("mov.b64 {%0, %1}, %2;" : "=f"(lo), "=f"(hi) : "l"(v));
    return make_float2(lo, hi);
}

// Stage one 128x128 weight matrix transposed into SMEM: wsh[j*WSTRIDE + i] = W[i][j].
// Coalesced float4 global reads; stride-129 scatter is near-conflict-free
// (bank = (j + i) mod 32, j distinct across lanes). One-shot cost.
__device__ __forceinline__ void stage_w(float* __restrict__ wsh,
                                        const float* __restrict__ wg, int tid) {
    const float4* g = reinterpret_cast<const float4*>(wg);
    const int j4 = tid & 31;        // which group of 4 columns
    const int i0 = tid >> 5;        // base row
#pragma unroll
    for (int k = 0; k < 16; k++) {
        const int i = i0 + k * 8;
        const float4 v = g[i * 32 + j4];
        const int j = j4 * 4;
        wsh[(j + 0) * WSTRIDE + i] = v.x;
        wsh[(j + 1) * WSTRIDE + i] = v.y;
        wsh[(j + 2) * WSTRIDE + i] = v.z;
        wsh[(j + 3) * WSTRIDE + i] = v.w;
    }
}

// One hidden layer (value + tangent fused in f32x2 lanes), relu + relu-mask.
// Tile: 8 output rows x 8 packed samples per thread (256 threads cover 128x128).
// j-loop is software-pipelined 2 deep: loads for j+1 issue before FMAs for j,
// so the 29-cycle LDS latency hides under 64 FFMA2 issues.
// Internal barrier separates GEMM reads from in-place overwrite; caller
// __syncthreads() after (and may stage next W before that barrier).
__device__ __forceinline__ void dense_relu_layer(ull* __restrict__ hd,
                                                 const float* __restrict__ wsh,
                                                 const float* __restrict__ bias_g,
                                                 int ibase, int bg) {
    ull acc[8][8];
#pragma unroll
    for (int r = 0; r < 8; r++)
#pragma unroll
        for (int p = 0; p < 8; p++) acc[r][p] = 0ull;

    const ull* hb = hd + bg;                 // b = bg + 16*p -> conflict-free
    const float* wb0 = wsh + ibase;

    // pipeline prologue: buffer A <- j=0
    float wA[8]; ull hA[8];
    float wB[8]; ull hB[8];
#pragma unroll
    for (int r = 0; r < 8; r++) wA[r] = wb0[r];
#pragma unroll
    for (int p = 0; p < 8; p++) hA[p] = hb[16 * p];

#pragma unroll 1
    for (int jj = 0; jj < HD / 2; jj++) {
        const int j1 = 2 * jj + 1;
        // prefetch j1 into B
        const float* wr1 = wsh + j1 * WSTRIDE + ibase;
#pragma unroll
        for (int r = 0; r < 8; r++) wB[r] = wr1[r];
#pragma unroll
        for (int p = 0; p < 8; p++) hB[p] = hb[j1 * BT + 16 * p];
        // FMAs for j = 2*jj (buffer A)
#pragma unroll
        for (int r = 0; r < 8; r++) {
            const ull wd = dup2(wA[r]);
#pragma unroll
            for (int p = 0; p < 8; p++)
                acc[r][p] = ffma2(wd, hA[p], acc[r][p]);
        }
        // prefetch j2 into A (wraps to row 0 on last iter; value unused)
        const int j2 = (2 * jj + 2) & (HD - 1);
        const float* wr2 = wsh + j2 * WSTRIDE + ibase;
#pragma unroll
        for (int r = 0; r < 8; r++) wA[r] = wr2[r];
#pragma unroll
        for (int p = 0; p < 8; p++) hA[p] = hb[j2 * BT + 16 * p];
        // FMAs for j1 (buffer B)
#pragma unroll
        for (int r = 0; r < 8; r++) {
            const ull wd = dup2(wB[r]);
#pragma unroll
            for (int p = 0; p < 8; p++)
                acc[r][p] = ffma2(wd, hB[p], acc[r][p]);
        }
    }

    float bb[8];
#pragma unroll
    for (int r = 0; r < 8; r++) bb[r] = bias_g[ibase + r];

    __syncthreads();   // all GEMM reads of hd/wsh complete before overwrite

#pragma unroll
    for (int r = 0; r < 8; r++) {
#pragma unroll
        for (int p = 0; p < 8; p++) {
            const float2 a = unpack2(acc[r][p]);
            const float pre = a.x + bb[r];
            const float h = pre > 0.f ? pre : 0.f;
            const float d = pre > 0.f ? a.y : 0.f;   // relu JVP mask
            hd[(ibase + r) * BT + bg + 16 * p] = pack2(h, d);
        }
    }
}

__global__ void __launch_bounds__(NTHREADS, 1)
sofa_kernel(const float* __restrict__ alpha,
            const float* __restrict__ w0g, const float* __restrict__ w1g,
            const float* __restrict__ w2g, const float* __restrict__ w3g,
            const float* __restrict__ b0g, const float* __restrict__ b1g,
            const float* __restrict__ b2g, const float* __restrict__ b3g,
            const float* __restrict__ sqrtag, float* __restrict__ out) {
    extern __shared__ char smem_raw[];
    ull*   hd  = reinterpret_cast<ull*>(smem_raw);
    float* wsh = reinterpret_cast<float*>(smem_raw + SMEM_HD);

    const int n    = blockIdx.y;
    const int tile = blockIdx.x;
    const int tid  = threadIdx.x;
    const int bg   = tid & 15;       // b-group: samples b = bg + 16*p
    const int ig   = tid >> 4;       // i-group: rows ibase..ibase+7
    const int ibase = ig * 8;
    const int base  = tile * BT;     // first (half-)sample of this tile

    // ---- layer 0: h0 = relu(w0*alpha + b0), dh0 = mask * w0 ; stage W1
    for (int idx = tid; idx < HD * BT; idx += NTHREADS) {
        const int i = idx >> 7;
        const int b = idx & 127;
        const float av  = alpha[base + b];     // base+b <= 2175 < 4097, in-bounds
        const float w   = w0g[n * HD + i];
        const float bb  = b0g[n * HD + i];
        const float pre = fmaf(w, av, bb);
        const float h   = pre > 0.f ? pre : 0.f;
        const float d   = pre > 0.f ? w : 0.f;
        hd[i * BT + b] = pack2(h, d);
    }
    stage_w(wsh, w1g + (size_t)n * HD * HD, tid);
    __syncthreads();

    // ---- layers 1, 2
    dense_relu_layer(hd, wsh, b1g + n * HD, ibase, bg);
    stage_w(wsh, w2g + (size_t)n * HD * HD, tid);   // wsh dead after internal barrier
    __syncthreads();

    dense_relu_layer(hd, wsh, b2g + n * HD, ibase, bg);
    __syncthreads();

    // ---- layer 3: out = w3 . h2 + b3 ; dout = w3 . dh2 ; then ellipse epilogue
    {
        const int bl = tid & 127;
        const int q  = tid >> 7;               // split reduction over i in halves
        const float* w3n = w3g + n * HD;
        float sv = 0.f, st = 0.f;
#pragma unroll 4
        for (int ii = q * 64; ii < q * 64 + 64; ii++) {
            const float wv = w3n[ii];
            const float2 h = unpack2(hd[ii * BT + bl]);
            sv = fmaf(wv, h.x, sv);
            st = fmaf(wv, h.y, st);
        }
        float* redv = wsh;                      // reuse weight SMEM (dead)
        float* redt = wsh + 2 * BT;
        redv[q * BT + bl] = sv;
        redt[q * BT + bl] = st;
        __syncthreads();

        if (tid < BT) {
            const int jg = base + tid;          // global half-sample index
            if (jg < BHALF) {
                const float v   = redv[tid] + redv[BT + tid] + b3g[n];
                const float t   = redt[tid] + redt[BT + tid];
                const float bsq = v * v;                 // b
                const float dbv = 2.f * v * t;           // db (chain rule of square)
                float a = sqrtag[n]; a = a * a;          // a_full
                const size_t NL = (size_t)NCUR * LFULL;

                float s, c;
                sincosf(alpha[jg], &s, &c);
                const size_t o = (size_t)n * LFULL + jg;
                out[o]          = a * (c - 1.f);         // xp
                out[NL + o]     = bsq * s;               // yp
                out[2 * NL + o] = -a * s;                // xp'
                out[3 * NL + o] = fmaf(bsq, c, dbv * s); // yp'

                if (jg < BHALF - 1) {                    // mirror l = 4096 - jg
                    const int l = 2 * (BHALF - 1) - jg;
                    float s2, c2;
                    sincosf(alpha[l], &s2, &c2);
                    const size_t o2 = (size_t)n * LFULL + l;
                    out[o2]          = a * (c2 - 1.f);
                    out[NL + o2]     = bsq * s2;
                    out[2 * NL + o2] = -a * s2;
                    out[3 * NL + o2] = fmaf(bsq, c2, -dbv * s2);  // db mirrored with -
                }
            }
        }
    }
}

extern "C" void kernel_launch(void* const* d_in, const int* in_sizes, int n_in,
                              void* d_out, int out_size) {
    (void)in_sizes; (void)n_in; (void)out_size;
    const float* alpha  = (const float*)d_in[0];
    const float* w0     = (const float*)d_in[1];
    const float* w1     = (const float*)d_in[2];
    const float* w2     = (const float*)d_in[3];
    const float* w3     = (const float*)d_in[4];
    const float* b0     = (const float*)d_in[5];
    const float* b1     = (const float*)d_in[6];
    const float* b2     = (const float*)d_in[7];
    const float* b3     = (const float*)d_in[8];
    const float* sqrt_a = (const float*)d_in[9];
    float* out = (float*)d_out;

    cudaFuncSetAttribute(sofa_kernel, cudaFuncAttributeMaxDynamicSharedMemorySize,
                         (int)SMEM_BYTES);

    dim3 grid(NTILES, NCUR);   // (17, 128)
    sofa_kernel<<<grid, NTHREADS, SMEM_BYTES>>>(alpha, w0, w1, w2, w3,
                                                b0, b1, b2, b3, sqrt_a, out);
}

// round 11
// speedup vs baseline: 1.9990x; 1.9480x over previous
#include <cuda_runtime.h>
#include <cuda_bf16.h>
#include <math.h>
#include <stdint.h>

// SofaNetEllipse R10: layers 1/2 as sm80-style warp MMAs (mma.sync m16n8k16
// bf16->fp32). 3-term bf16 hi/lo split (Whi*Hhi + Wlo*Hhi + Whi*Hlo) for
// fp32-class accuracy. M=128 (hidden i), N=256 (128 samples x {val,tan}
// interleaved), K=128.
// R9->R10 fix: B operand uses NON-transposed ldmatrix. For row.col mma the B
// fragment needs thread t to hold (n=t/4, k=2*(t%4)+{0,1}); K-major [c][k]
// SMEM + plain ldmatrix delivers exactly that. The .trans variant swapped n/k
// within each 8x8 tile (output 0 exact, output 1 rel_err 0.407).

typedef unsigned long long ull;

namespace {
constexpr int HD = 128, NCUR = 128, LFULL = 4097, BHALF = 2049, BT = 128;
constexpr int NTILES   = 17;
constexpr int NTHREADS = 512;
constexpr int AS = 136;                 // A row stride in bf16 units
constexpr int BS = 136;                 // B row stride
constexpr int OFF_AHI = 0;
constexpr int OFF_ALO = OFF_AHI + HD * AS * 2;        // 34816
constexpr int OFF_BHI = OFF_ALO + HD * AS * 2;        // 69632
constexpr int OFF_BLO = OFF_BHI + 2 * BT * BS * 2;    // 139264
constexpr int OFF_END = OFF_BLO + 2 * BT * BS * 2;    // 208896
constexpr int OFF_SCR = OFF_BHI;        // layer-3 scratch float2[s][i], aliases B (dead)
constexpr int SCRS = 129;               // scratch row stride (float2 units)
constexpr int SMEM_BYTES = OFF_END;     // 208896 <= 227KB
}

__device__ __forceinline__ uint32_t smem_u32(const void* p) {
    uint32_t a;
    asm("{ .reg .u64 t; cvta.to.shared.u64 t, %1; cvt.u32.u64 %0, t; }" : "=r"(a) : "l"(p));
    return a;
}
__device__ __forceinline__ void ldsm4(uint32_t (&r)[4], uint32_t addr) {
    asm volatile("ldmatrix.sync.aligned.m8n8.x4.shared.b16 {%0,%1,%2,%3}, [%4];"
                 : "=r"(r[0]), "=r"(r[1]), "=r"(r[2]), "=r"(r[3]) : "r"(addr));
}
__device__ __forceinline__ void mma_bf16(float (&d)[4], const uint32_t (&a)[4],
                                         uint32_t b0, uint32_t b1) {
    asm volatile(
        "mma.sync.aligned.m16n8k16.row.col.f32.bf16.bf16.f32 "
        "{%0,%1,%2,%3}, {%4,%5,%6,%7}, {%8,%9}, {%0,%1,%2,%3};"
        : "+f"(d[0]), "+f"(d[1]), "+f"(d[2]), "+f"(d[3])
        : "r"(a[0]), "r"(a[1]), "r"(a[2]), "r"(a[3]), "r"(b0), "r"(b1));
}
// bf16 hi/lo split store: hi = rn(v); lo = rn(v - hi)
__device__ __forceinline__ void split_store(char* sm, int off_hi, int off_lo,
                                            int elt, float v) {
    const __nv_bfloat16 hi = __float2bfloat16(v);
    const __nv_bfloat16 lo = __float2bfloat16(v - __bfloat162float(hi));
    *(__nv_bfloat16*)(sm + off_hi + 2 * elt) = hi;
    *(__nv_bfloat16*)(sm + off_lo + 2 * elt) = lo;
}

// One layer GEMM: acc[nt][4] += (3-term bf16) W x H^T for this warp's
// 16-row M-tile (mt) and 128-col N-half (nq). A row-major [i][k], B = H
// rows [c][k] (mma row.col => both K-major, both plain ldmatrix).
__device__ __forceinline__ void gemm_layer(float (&acc)[16][4], uint32_t sb,
                                           int mt, int nq, int lane) {
    const int rowa = 16 * mt + (lane & 15);
    const uint32_t a_off = (uint32_t)(rowa * AS) * 2u + (uint32_t)((lane >> 4) << 4);
    const uint32_t a_hi = sb + OFF_AHI + a_off;
    const uint32_t a_lo = sb + OFF_ALO + a_off;
    // B x4 grouping: lanes 0-7 -> (n0..n0+7, k0), 8-15 -> (n0..n0+7, k8),
    // 16-23 -> (n0+8..15, k0), 24-31 -> (n0+8..15, k8)
    const int crow = 128 * nq + (lane & 7) + ((lane & 16) >> 1);
    const uint32_t b_off = (uint32_t)(crow * BS) * 2u + ((lane & 8) ? 16u : 0u);
    const uint32_t b_hi = sb + OFF_BHI + b_off;
    const uint32_t b_lo = sb + OFF_BLO + b_off;

#pragma unroll 1
    for (int kk = 0; kk < 8; kk++) {
        const uint32_t ko = (uint32_t)kk * 32u;
        uint32_t ah[4], al[4];
        ldsm4(ah, a_hi + ko);
        ldsm4(al, a_lo + ko);
#pragma unroll
        for (int g = 0; g < 4; g++) {
            // group g: ntiles 4g..4g+3 = c-rows [32g, 32g+32)
            const uint32_t go = (uint32_t)(g * 32 * BS) * 2u + ko;
            uint32_t bh0[4], bh1[4], bl0[4], bl1[4];
            ldsm4(bh0, b_hi + go);
            ldsm4(bh1, b_hi + go + 16u * BS * 2u);
            ldsm4(bl0, b_lo + go);
            ldsm4(bl1, b_lo + go + 16u * BS * 2u);
            // term 0: Whi * Hhi
            mma_bf16(acc[4 * g + 0], ah, bh0[0], bh0[1]);
            mma_bf16(acc[4 * g + 1], ah, bh0[2], bh0[3]);
            mma_bf16(acc[4 * g + 2], ah, bh1[0], bh1[1]);
            mma_bf16(acc[4 * g + 3], ah, bh1[2], bh1[3]);
            // term 1: Wlo * Hhi
            mma_bf16(acc[4 * g + 0], al, bh0[0], bh0[1]);
            mma_bf16(acc[4 * g + 1], al, bh0[2], bh0[3]);
            mma_bf16(acc[4 * g + 2], al, bh1[0], bh1[1]);
            mma_bf16(acc[4 * g + 3], al, bh1[2], bh1[3]);
            // term 2: Whi * Hlo
            mma_bf16(acc[4 * g + 0], ah, bl0[0], bl0[1]);
            mma_bf16(acc[4 * g + 1], ah, bl0[2], bl0[3]);
            mma_bf16(acc[4 * g + 2], ah, bl1[0], bl1[1]);
            mma_bf16(acc[4 * g + 3], ah, bl1[2], bl1[3]);
        }
    }
}

__global__ void __launch_bounds__(NTHREADS, 1)
sofa_kernel(const float* __restrict__ alpha,
            const float* __restrict__ w0g, const float* __restrict__ w1g,
            const float* __restrict__ w2g, const float* __restrict__ w3g,
            const float* __restrict__ b0g, const float* __restrict__ b1g,
            const float* __restrict__ b2g, const float* __restrict__ b3g,
            const float* __restrict__ sqrtag, float* __restrict__ out) {
    extern __shared__ char smem[];
    const uint32_t sb = smem_u32(smem);
    const int tid = threadIdx.x;
    const int wid = tid >> 5, lane = tid & 31;
    const int mt = wid & 7, nq = wid >> 3;          // warp = (M-tile, N-half)
    const int g8 = lane >> 2, t4 = lane & 3;        // D frag coords
    const int n = blockIdx.y, tile = blockIdx.x, base = tile * BT;

    // ---- layer 0: fill B with {h0, dh0} (c = 2s val / 2s+1 tan), stage W1 -> A
    {
        const int c = tid >> 1;                 // 0..255
        const int j0 = (tid & 1) * 64;
        const int s = c >> 1, vt = c & 1;
        const float a = alpha[base + s];        // <= 2175 < 4097
        const float* w0n = w0g + n * HD;
        const float* b0n = b0g + n * HD;
#pragma unroll 4
        for (int j = j0; j < j0 + 64; j++) {
            const float w = w0n[j];
            const float pre = fmaf(w, a, b0n[j]);
            const float v = vt ? (pre > 0.f ? w : 0.f) : (pre > 0.f ? pre : 0.f);
            split_store(smem, OFF_BHI, OFF_BLO, c * BS + j, v);
        }
    }
    for (int idx = tid; idx < HD * HD; idx += NTHREADS) {
        const int i = idx >> 7, j = idx & 127;
        split_store(smem, OFF_AHI, OFF_ALO, i * AS + j, w1g[(size_t)n * HD * HD + idx]);
    }
    __syncthreads();

    // ---- layer 1 GEMM
    float acc[16][4];
#pragma unroll
    for (int a_ = 0; a_ < 16; a_++)
#pragma unroll
        for (int b_ = 0; b_ < 4; b_++) acc[a_][b_] = 0.f;
    gemm_layer(acc, sb, mt, nq, lane);
    __syncthreads();    // all GEMM reads of A/B done before overwrite

    // ---- layer-1 epilogue: bias+relu+mask, split back into B; stage W2 -> A
    {
        const int i0 = 16 * mt + g8, i1 = i0 + 8;
        const float bias0 = b1g[n * HD + i0];
        const float bias1 = b1g[n * HD + i1];
#pragma unroll
        for (int nt = 0; nt < 16; nt++) {
            const int ce = 128 * nq + 8 * nt + 2 * t4;   // even col = val, +1 = tan
            const float p0 = acc[nt][0] + bias0;
            const float h0 = p0 > 0.f ? p0 : 0.f;
            const float d0 = p0 > 0.f ? acc[nt][1] : 0.f;
            const float p1 = acc[nt][2] + bias1;
            const float h1 = p1 > 0.f ? p1 : 0.f;
            const float d1 = p1 > 0.f ? acc[nt][3] : 0.f;
            split_store(smem, OFF_BHI, OFF_BLO, ce * BS + i0, h0);
            split_store(smem, OFF_BHI, OFF_BLO, (ce + 1) * BS + i0, d0);
            split_store(smem, OFF_BHI, OFF_BLO, ce * BS + i1, h1);
            split_store(smem, OFF_BHI, OFF_BLO, (ce + 1) * BS + i1, d1);
        }
    }
    for (int idx = tid; idx < HD * HD; idx += NTHREADS) {
        const int i = idx >> 7, j = idx & 127;
        split_store(smem, OFF_AHI, OFF_ALO, i * AS + j, w2g[(size_t)n * HD * HD + idx]);
    }
    __syncthreads();

    // ---- layer 2 GEMM
#pragma unroll
    for (int a_ = 0; a_ < 16; a_++)
#pragma unroll
        for (int b_ = 0; b_ < 4; b_++) acc[a_][b_] = 0.f;
    gemm_layer(acc, sb, mt, nq, lane);
    __syncthreads();    // B reads done; scratch aliases B

    // ---- layer-2 epilogue: fp32 {h2, dh2} -> scratch [s][i]
    {
        float2* scr = (float2*)(smem + OFF_SCR);
        const int i0 = 16 * mt + g8, i1 = i0 + 8;
        const float bias0 = b2g[n * HD + i0];
        const float bias1 = b2g[n * HD + i1];
#pragma unroll
        for (int nt = 0; nt < 16; nt++) {
            const int s = 64 * nq + 4 * nt + t4;
            const float p0 = acc[nt][0] + bias0;
            const float h0 = p0 > 0.f ? p0 : 0.f;
            const float d0 = p0 > 0.f ? acc[nt][1] : 0.f;
            const float p1 = acc[nt][2] + bias1;
            const float h1 = p1 > 0.f ? p1 : 0.f;
            const float d1 = p1 > 0.f ? acc[nt][3] : 0.f;
            scr[s * SCRS + i0] = make_float2(h0, d0);
            scr[s * SCRS + i1] = make_float2(h1, d1);
        }
    }
    __syncthreads();

    // ---- layer 3 + ellipse/trig epilogue
    {
        const int bl = tid & 127;               // sample
        const int q  = tid >> 7;                // quarter of the i-reduction
        const float* w3n = w3g + n * HD;
        const float2* srow = (const float2*)(smem + OFF_SCR) + (size_t)bl * SCRS;
        float sv = 0.f, st = 0.f;
#pragma unroll 8
        for (int ii = q * 32; ii < q * 32 + 32; ii++) {
            const float wv = w3n[ii];
            const float2 h = srow[ii];
            sv = fmaf(wv, h.x, sv);
            st = fmaf(wv, h.y, st);
        }
        float* redv = (float*)(smem + OFF_AHI);  // A region dead
        float* redt = redv + 512;
        redv[q * BT + bl] = sv;
        redt[q * BT + bl] = st;
        __syncthreads();

        if (tid < BT) {
            const int jg = base + tid;
            if (jg < BHALF) {
                const float v = redv[tid] + redv[BT + tid] + redv[2 * BT + tid]
                              + redv[3 * BT + tid] + b3g[n];
                const float t = redt[tid] + redt[BT + tid] + redt[2 * BT + tid]
                              + redt[3 * BT + tid];
                const float bsq = v * v;
                const float dbv = 2.f * v * t;
                float a = sqrtag[n]; a = a * a;
                const size_t NL = (size_t)NCUR * LFULL;

                float s, c;
                sincosf(alpha[jg], &s, &c);
                const size_t o = (size_t)n * LFULL + jg;
                out[o]          = a * (c - 1.f);
                out[NL + o]     = bsq * s;
                out[2 * NL + o] = -a * s;
                out[3 * NL + o] = fmaf(bsq, c, dbv * s);

                if (jg < BHALF - 1) {               // mirror l = 4096 - jg
                    const int l = 2 * (BHALF - 1) - jg;
                    float s2, c2;
                    sincosf(alpha[l], &s2, &c2);
                    const size_t o2 = (size_t)n * LFULL + l;
                    out[o2]          = a * (c2 - 1.f);
                    out[NL + o2]     = bsq * s2;
                    out[2 * NL + o2] = -a * s2;
                    out[3 * NL + o2] = fmaf(bsq, c2, -dbv * s2);
                }
            }
        }
    }
}

extern "C" void kernel_launch(void* const* d_in, const int* in_sizes, int n_in,
                              void* d_out, int out_size) {
    (void)in_sizes; (void)n_in; (void)out_size;
    const float* alpha  = (const float*)d_in[0];
    const float* w0     = (const float*)d_in[1];
    const float* w1     = (const float*)d_in[2];
    const float* w2     = (const float*)d_in[3];
    const float* w3     = (const float*)d_in[4];
    const float* b0     = (const float*)d_in[5];
    const float* b1     = (const float*)d_in[6];
    const float* b2     = (const float*)d_in[7];
    const float* b3     = (const float*)d_in[8];
    const float* sqrt_a = (const float*)d_in[9];
    float* out = (float*)d_out;

    cudaFuncSetAttribute(sofa_kernel, cudaFuncAttributeMaxDynamicSharedMemorySize,
                         SMEM_BYTES);

    dim3 grid(NTILES, NCUR);   // (17, 128)
    sofa_kernel<<<grid, NTHREADS, SMEM_BYTES>>>(alpha, w0, w1, w2, w3,
                                                b0, b1, b2, b3, sqrt_a, out);
}

// round 12
// speedup vs baseline: 2.0286x; 1.0148x over previous
#include <cuda_runtime.h>
#include <cuda_bf16.h>
#include <math.h>
#include <stdint.h>

// SofaNetEllipse R11: HMMA (mma.sync m16n8k16 bf16, 3-term hi/lo split) with
// wide-store data movement everywhere:
//  - B stored [k][c] (528B padded rows) -> ldmatrix.trans (same fragments)
//  - epilogue-1 writes via stmatrix.m8n8.x4 (sm_90 baseline)
//  - W1/W2 pre-split to bf16 hi/lo in a prologue kernel; staged via cp.async
//  - layer-0 fill packed to STS.128; trig tail spread over all 512 threads

typedef unsigned long long ull;

namespace {
constexpr int HD = 128, NCUR = 128, LFULL = 4097, BHALF = 2049, BT = 128;
constexpr int NTILES   = 17;
constexpr int NTHREADS = 512;
constexpr int AS  = 136;                // A row stride, bf16 units (272B)
constexpr int BKB = 528;                // B k-row stride, bytes (264 bf16)
constexpr int OFF_AHI = 0;
constexpr int OFF_ALO = OFF_AHI + HD * AS * 2;     // 34816
constexpr int OFF_BHI = OFF_ALO + HD * AS * 2;     // 69632
constexpr int OFF_BLO = OFF_BHI + HD * BKB;        // 137216
constexpr int OFF_END = OFF_BLO + HD * BKB;        // 204800
constexpr int OFF_SCR = OFF_BHI;        // layer-3 scratch float2[s][i] (aliases B, dead)
constexpr int SCRS = 129;               // scratch row stride (float2 units)
constexpr int SMEM_BYTES = OFF_END;
}

// pre-split bf16 weights (written by prologue kernel each launch)
__device__ __nv_bfloat16 g_w1hi[NCUR * HD * HD];
__device__ __nv_bfloat16 g_w1lo[NCUR * HD * HD];
__device__ __nv_bfloat16 g_w2hi[NCUR * HD * HD];
__device__ __nv_bfloat16 g_w2lo[NCUR * HD * HD];

__device__ __forceinline__ uint32_t smem_u32(const void* p) {
    uint32_t a;
    asm("{ .reg .u64 t; cvta.to.shared.u64 t, %1; cvt.u32.u64 %0, t; }" : "=r"(a) : "l"(p));
    return a;
}
__device__ __forceinline__ void ldsm4(uint32_t (&r)[4], uint32_t addr) {
    asm volatile("ldmatrix.sync.aligned.m8n8.x4.shared.b16 {%0,%1,%2,%3}, [%4];"
                 : "=r"(r[0]), "=r"(r[1]), "=r"(r[2]), "=r"(r[3]) : "r"(addr));
}
__device__ __forceinline__ void ldsm4t(uint32_t (&r)[4], uint32_t addr) {
    asm volatile("ldmatrix.sync.aligned.m8n8.x4.trans.shared.b16 {%0,%1,%2,%3}, [%4];"
                 : "=r"(r[0]), "=r"(r[1]), "=r"(r[2]), "=r"(r[3]) : "r"(addr));
}
__device__ __forceinline__ void stsm4(uint32_t addr, uint32_t r0, uint32_t r1,
                                      uint32_t r2, uint32_t r3) {
    asm volatile("stmatrix.sync.aligned.m8n8.x4.shared.b16 [%0], {%1,%2,%3,%4};"
                 :: "r"(addr), "r"(r0), "r"(r1), "r"(r2), "r"(r3) : "memory");
}
__device__ __forceinline__ void mma_bf16(float (&d)[4], const uint32_t (&a)[4],
                                         uint32_t b0, uint32_t b1) {
    asm volatile(
        "mma.sync.aligned.m16n8k16.row.col.f32.bf16.bf16.f32 "
        "{%0,%1,%2,%3}, {%4,%5,%6,%7}, {%8,%9}, {%0,%1,%2,%3};"
        : "+f"(d[0]), "+f"(d[1]), "+f"(d[2]), "+f"(d[3])
        : "r"(a[0]), "r"(a[1]), "r"(a[2]), "r"(a[3]), "r"(b0), "r"(b1));
}
__device__ __forceinline__ void cpasync16(uint32_t dst, const void* src) {
    asm volatile("cp.async.ca.shared.global [%0], [%1], 16;" :: "r"(dst), "l"(src) : "memory");
}
__device__ __forceinline__ void cpasync_wait_all() {
    asm volatile("cp.async.commit_group;\n\tcp.async.wait_group 0;" ::: "memory");
}
__device__ __forceinline__ uint32_t packh(__nv_bfloat16 a, __nv_bfloat16 b) {
    uint16_t ua = *(uint16_t*)&a, ub = *(uint16_t*)&b;
    return (uint32_t)ua | ((uint32_t)ub << 16);
}
// split pair (x,y) into packed bf16x2 hi and lo words (lo = residual)
__device__ __forceinline__ void split2(float x, float y, uint32_t& hi, uint32_t& lo) {
    const __nv_bfloat16 hx = __float2bfloat16(x), hy = __float2bfloat16(y);
    const __nv_bfloat16 lx = __float2bfloat16(x - __bfloat162float(hx));
    const __nv_bfloat16 ly = __float2bfloat16(y - __bfloat162float(hy));
    hi = packh(hx, hy);
    lo = packh(lx, ly);
}

// ---- prologue: split fp32 W1/W2 into bf16 hi/lo global buffers
__global__ void split_w_kernel(const float* __restrict__ w1, const float* __restrict__ w2) {
    const int idx = blockIdx.x * blockDim.x + threadIdx.x;
    if (idx < NCUR * HD * HD) {
        float v = w1[idx];
        __nv_bfloat16 h = __float2bfloat16(v);
        g_w1hi[idx] = h;
        g_w1lo[idx] = __float2bfloat16(v - __bfloat162float(h));
        v = w2[idx];
        h = __float2bfloat16(v);
        g_w2hi[idx] = h;
        g_w2lo[idx] = __float2bfloat16(v - __bfloat162float(h));
    }
}

// stage one pre-split W into A region via cp.async (caller: commit/wait + barrier)
__device__ __forceinline__ void stage_w_async(uint32_t sb, const __nv_bfloat16* ghi,
                                              const __nv_bfloat16* glo, int tid) {
    const int i = tid >> 2, ch = tid & 3;            // 32-k chunk
    const __nv_bfloat16* shi = ghi + i * HD + ch * 32;
    const __nv_bfloat16* slo = glo + i * HD + ch * 32;
    const uint32_t dhi = sb + OFF_AHI + (uint32_t)(i * 272 + ch * 64);
    const uint32_t dlo = sb + OFF_ALO + (uint32_t)(i * 272 + ch * 64);
#pragma unroll
    for (int q = 0; q < 4; q++) {
        cpasync16(dhi + 16 * q, shi + 8 * q);
        cpasync16(dlo + 16 * q, slo + 8 * q);
    }
}

// One layer GEMM: 3-term bf16 W x H^T. A [i][k] row-major (plain ldmatrix);
// B [k][c] (ldmatrix.trans -> identical fragments to [c][k]+plain).
__device__ __forceinline__ void gemm_layer(float (&acc)[16][4], uint32_t sb,
                                           int mt, int nq, int lane) {
    const int rowa = 16 * mt + (lane & 15);
    const uint32_t a_off = (uint32_t)(rowa * 272) + (uint32_t)((lane >> 4) << 4);
    const uint32_t a_hi = sb + OFF_AHI + a_off;
    const uint32_t a_lo = sb + OFF_ALO + a_off;
    // lane -> (k within 16-tile, c offset): r0=(c0..7,k0..7) r1=(c0..7,k8..15)
    // r2=(c8..15,k0..7) r3=(c8..15,k8..15)
    const int krow = (lane & 7) + (lane & 8);
    const int colb = 128 * nq + ((lane & 16) >> 1);
    const uint32_t b_off = (uint32_t)(krow * BKB) + (uint32_t)(colb * 2);
    const uint32_t b_hi = sb + OFF_BHI + b_off;
    const uint32_t b_lo = sb + OFF_BLO + b_off;

#pragma unroll 1
    for (int kk = 0; kk < 8; kk++) {
        const uint32_t ka = (uint32_t)kk * 32u;
        const uint32_t kb = (uint32_t)kk * (16u * BKB);
        uint32_t ah[4], al[4];
        ldsm4(ah, a_hi + ka);
        ldsm4(al, a_lo + ka);
#pragma unroll
        for (int g = 0; g < 4; g++) {
            const uint32_t go = kb + (uint32_t)(64 * g);   // +32 c-cols per g
            uint32_t bh0[4], bh1[4], bl0[4], bl1[4];
            ldsm4t(bh0, b_hi + go);
            ldsm4t(bh1, b_hi + go + 32u);                  // +16 c-cols
            ldsm4t(bl0, b_lo + go);
            ldsm4t(bl1, b_lo + go + 32u);
            mma_bf16(acc[4 * g + 0], ah, bh0[0], bh0[1]);
            mma_bf16(acc[4 * g + 1], ah, bh0[2], bh0[3]);
            mma_bf16(acc[4 * g + 2], ah, bh1[0], bh1[1]);
            mma_bf16(acc[4 * g + 3], ah, bh1[2], bh1[3]);
            mma_bf16(acc[4 * g + 0], al, bh0[0], bh0[1]);
            mma_bf16(acc[4 * g + 1], al, bh0[2], bh0[3]);
            mma_bf16(acc[4 * g + 2], al, bh1[0], bh1[1]);
            mma_bf16(acc[4 * g + 3], al, bh1[2], bh1[3]);
            mma_bf16(acc[4 * g + 0], ah, bl0[0], bl0[1]);
            mma_bf16(acc[4 * g + 1], ah, bl0[2], bl0[3]);
            mma_bf16(acc[4 * g + 2], ah, bl1[0], bl1[1]);
            mma_bf16(acc[4 * g + 3], ah, bl1[2], bl1[3]);
        }
    }
}

__global__ void __launch_bounds__(NTHREADS, 1)
sofa_kernel(const float* __restrict__ alpha,
            const float* __restrict__ w0g, const float* __restrict__ w3g,
            const float* __restrict__ b0g, const float* __restrict__ b1g,
            const float* __restrict__ b2g, const float* __restrict__ b3g,
            const float* __restrict__ sqrtag, float* __restrict__ out) {
    extern __shared__ char smem[];
    const uint32_t sb = smem_u32(smem);
    const int tid = threadIdx.x;
    const int wid = tid >> 5, lane = tid & 31;
    const int mt = wid & 7, nq = wid >> 3;          // warp = (M-tile, N-half)
    const int g8 = lane >> 2, t4 = lane & 3;        // D frag coords
    const int n = blockIdx.y, tile = blockIdx.x, base = tile * BT;
    const size_t woff = (size_t)n * HD * HD;

    // ---- layer 0: B[k=j][c=2s|2s+1] = {h0, dh0}, packed STS.128; stage W1 (cp.async)
    stage_w_async(sb, g_w1hi + woff, g_w1lo + woff, tid);
    {
        const float* w0n = w0g + n * HD;
        const float* b0n = b0g + n * HD;
#pragma unroll 1
        for (int t = tid; t < 2048; t += NTHREADS) {    // 4 tasks: (j, 8-sample group)
            const int j = t >> 4, sg = t & 15;
            const float w = w0n[j], bb = b0n[j];
            uint32_t hw[8], lw[8];
#pragma unroll
            for (int q = 0; q < 8; q++) {
                const float a = alpha[base + sg * 8 + q];   // <= 2175 < 4097
                const float pre = fmaf(w, a, bb);
                const float h = pre > 0.f ? pre : 0.f;
                const float d = pre > 0.f ? w : 0.f;
                split2(h, d, hw[q], lw[q]);
            }
            const int rowb = j * BKB + sg * 32;             // c0 = 16*sg -> 32*sg bytes
            *(uint4*)(smem + OFF_BHI + rowb)      = make_uint4(hw[0], hw[1], hw[2], hw[3]);
            *(uint4*)(smem + OFF_BHI + rowb + 16) = make_uint4(hw[4], hw[5], hw[6], hw[7]);
            *(uint4*)(smem + OFF_BLO + rowb)      = make_uint4(lw[0], lw[1], lw[2], lw[3]);
            *(uint4*)(smem + OFF_BLO + rowb + 16) = make_uint4(lw[4], lw[5], lw[6], lw[7]);
        }
    }
    cpasync_wait_all();
    __syncthreads();

    // ---- layer 1 GEMM
    float acc[16][4];
#pragma unroll
    for (int a_ = 0; a_ < 16; a_++)
#pragma unroll
        for (int b_ = 0; b_ < 4; b_++) acc[a_][b_] = 0.f;
    gemm_layer(acc, sb, mt, nq, lane);
    __syncthreads();    // all GEMM reads of A/B done before overwrite

    // ---- layer-1 epilogue via stmatrix; stage W2 (cp.async)
    stage_w_async(sb, g_w2hi + woff, g_w2lo + woff, tid);
    {
        const int i0 = 16 * mt + g8;
        const float bias0 = b1g[n * HD + i0];
        const float bias1 = b1g[n * HD + i0 + 8];
        // stmatrix x4 lane addressing: lanes 0-7 tile(i-lo,v), 8-15 (i-hi,v),
        // 16-23 (i-lo,v+1), 24-31 (i-hi,v+1)
        const int h8 = (lane >> 3) & 1, v8 = (lane >> 4) & 1, lr = lane & 7;
        const uint32_t st_hi = sb + OFF_BHI
            + (uint32_t)((16 * mt + 8 * h8 + lr) * BKB) + (uint32_t)((128 * nq + 8 * v8) * 2);
        const uint32_t st_lo = st_hi + (uint32_t)(OFF_BLO - OFF_BHI);
#pragma unroll
        for (int v = 0; v < 16; v += 2) {
            uint32_t h0, h1, h2, h3, l0, l1, l2, l3;
            {
                const float p = acc[v][0] + bias0;
                split2(p > 0.f ? p : 0.f, p > 0.f ? acc[v][1] : 0.f, h0, l0);
            }
            {
                const float p = acc[v][2] + bias1;
                split2(p > 0.f ? p : 0.f, p > 0.f ? acc[v][3] : 0.f, h1, l1);
            }
            {
                const float p = acc[v + 1][0] + bias0;
                split2(p > 0.f ? p : 0.f, p > 0.f ? acc[v + 1][1] : 0.f, h2, l2);
            }
            {
                const float p = acc[v + 1][2] + bias1;
                split2(p > 0.f ? p : 0.f, p > 0.f ? acc[v + 1][3] : 0.f, h3, l3);
            }
            stsm4(st_hi + (uint32_t)(v * 16), h0, h1, h2, h3);
            stsm4(st_lo + (uint32_t)(v * 16), l0, l1, l2, l3);
        }
    }
    cpasync_wait_all();
    __syncthreads();

    // ---- layer 2 GEMM
#pragma unroll
    for (int a_ = 0; a_ < 16; a_++)
#pragma unroll
        for (int b_ = 0; b_ < 4; b_++) acc[a_][b_] = 0.f;
    gemm_layer(acc, sb, mt, nq, lane);
    __syncthreads();    // B reads done; scratch aliases B

    // ---- layer-2 epilogue: fp32 {h2, dh2} -> scratch [s][i]
    {
        float2* scr = (float2*)(smem + OFF_SCR);
        const int i0 = 16 * mt + g8, i1 = i0 + 8;
        const float bias0 = b2g[n * HD + i0];
        const float bias1 = b2g[n * HD + i1];
#pragma unroll
        for (int nt = 0; nt < 16; nt++) {
            const int s = 64 * nq + 4 * nt + t4;
            const float p0 = acc[nt][0] + bias0;
            const float h0 = p0 > 0.f ? p0 : 0.f;
            const float d0 = p0 > 0.f ? acc[nt][1] : 0.f;
            const float p1 = acc[nt][2] + bias1;
            const float h1 = p1 > 0.f ? p1 : 0.f;
            const float d1 = p1 > 0.f ? acc[nt][3] : 0.f;
            scr[s * SCRS + i0] = make_float2(h0, d0);
            scr[s * SCRS + i1] = make_float2(h1, d1);
        }
    }
    __syncthreads();

    // ---- layer 3 reduction
    {
        const int bl = tid & 127;               // sample
        const int q  = tid >> 7;                // quarter of i-reduction
        const float* w3n = w3g + n * HD;
        const float2* srow = (const float2*)(smem + OFF_SCR) + (size_t)bl * SCRS;
        float sv = 0.f, st = 0.f;
#pragma unroll 8
        for (int ii = q * 32; ii < q * 32 + 32; ii++) {
            const float wv = w3n[ii];
            const float2 h = srow[ii];
            sv = fmaf(wv, h.x, sv);
            st = fmaf(wv, h.y, st);
        }
        float* redv = (float*)(smem + OFF_AHI);  // A region dead
        float* redt = redv + 512;
        redv[q * BT + bl] = sv;
        redt[q * BT + bl] = st;
    }
    __syncthreads();

    // ---- trig epilogue: 512 threads, (sample, output-kind) split
    {
        const int bl = tid & 127, kind = tid >> 7;
        const int jg = base + bl;
        if (jg < BHALF) {
            const float* redv = (const float*)(smem + OFF_AHI);
            const float* redt = redv + 512;
            const float v = redv[bl] + redv[BT + bl] + redv[2 * BT + bl]
                          + redv[3 * BT + bl] + b3g[n];
            const float t = redt[bl] + redt[BT + bl] + redt[2 * BT + bl]
                          + redt[3 * BT + bl];
            const float bsq = v * v;
            const float dbv = 2.f * v * t;
            float a = sqrtag[n]; a = a * a;
            const size_t NL = (size_t)NCUR * LFULL;
            const size_t o  = (size_t)n * LFULL + jg;
            float s, c;
            sincosf(alpha[jg], &s, &c);
            const bool mir = (jg < BHALF - 1);
            const int l = 2 * (BHALF - 1) - jg;
            float s2 = 0.f, c2 = 0.f;
            if (mir) sincosf(alpha[l], &s2, &c2);
            const size_t o2 = (size_t)n * LFULL + l;
            switch (kind) {
                case 0:
                    out[o] = a * (c - 1.f);
                    if (mir) out[o2] = a * (c2 - 1.f);
                    break;
                case 1:
                    out[NL + o] = bsq * s;
                    if (mir) out[NL + o2] = bsq * s2;
                    break;
                case 2:
                    out[2 * NL + o] = -a * s;
                    if (mir) out[2 * NL + o2] = -a * s2;
                    break;
                default:
                    out[3 * NL + o] = fmaf(bsq, c, dbv * s);
                    if (mir) out[3 * NL + o2] = fmaf(bsq, c2, -dbv * s2);
            }
        }
    }
}

extern "C" void kernel_launch(void* const* d_in, const int* in_sizes, int n_in,
                              void* d_out, int out_size) {
    (void)in_sizes; (void)n_in; (void)out_size;
    const float* alpha  = (const float*)d_in[0];
    const float* w0     = (const float*)d_in[1];
    const float* w1     = (const float*)d_in[2];
    const float* w2     = (const float*)d_in[3];
    const float* w3     = (const float*)d_in[4];
    const float* b0     = (const float*)d_in[5];
    const float* b1     = (const float*)d_in[6];
    const float* b2     = (const float*)d_in[7];
    const float* b3     = (const float*)d_in[8];
    const float* sqrt_a = (const float*)d_in[9];
    float* out = (float*)d_out;

    split_w_kernel<<<(NCUR * HD * HD + 255) / 256, 256>>>(w1, w2);

    cudaFuncSetAttribute(sofa_kernel, cudaFuncAttributeMaxDynamicSharedMemorySize,
                         SMEM_BYTES);
    dim3 grid(NTILES, NCUR);   // (17, 128)
    sofa_kernel<<<grid, NTHREADS, SMEM_BYTES>>>(alpha, w0, w3,
                                                b0, b1, b2, b3, sqrt_a, out);
}